// round 10
// baseline (speedup 1.0000x reference)
#include <cuda_runtime.h>
#include <cuda_fp16.h>
#include <cstdint>

// Problem constants
#define NROWS 65536
#define DIM   256
#define NE    8192

// Output packing (float32, reference return order)
#define XQ_OFF   0ULL
#define LOSS_OFF 16777216ULL
#define IDX_OFF  16777217ULL
#define D_OFF    16842753ULL

// ---------------------------------------------------------------------------
// Device scratch
// ---------------------------------------------------------------------------
__device__ uint2 g_xq[NROWS * 32];   // int8 x rows (16MB)
__device__ uint2 g_eq[NE * 32];      // int8 emb rows (2MB)
__device__ __align__(16) float g_xnorm[NROWS];
__device__ __align__(16) float g_enorm[NE];
__device__ __align__(16) float g_xscale[NROWS];  // max|x_r|/127
__device__ __align__(16) float g_escale[NE];     // -2*max|e_r|/127 (folded)
__device__ int    g_cand[NROWS * 24];
__device__ double g_losssum;

// ---------------------------------------------------------------------------
// helpers
// ---------------------------------------------------------------------------
__device__ __forceinline__ uint32_t smem_to_u32(const void* p) {
    uint32_t a;
    asm("{ .reg .u64 t; cvta.to.shared.u64 t, %1; cvt.u32.u64 %0, t; }"
        : "=r"(a) : "l"(p));
    return a;
}
__device__ __forceinline__ uint64_t to_global(const void* p) {
    uint64_t g;
    asm("cvta.to.global.u64 %0, %1;" : "=l"(g) : "l"(p));
    return g;
}
#define CP_ASYNC_16(dst, src) \
    asm volatile("cp.async.cg.shared.global [%0], [%1], 16;" :: "r"(dst), "l"(src))
#define CP_COMMIT() asm volatile("cp.async.commit_group;" ::: "memory")
#define CP_WAIT(n)  asm volatile("cp.async.wait_group %0;" :: "n"(n) : "memory")

#define LDMATRIX_X4(r, addr) \
    asm volatile("ldmatrix.sync.aligned.m8n8.x4.shared.b16 {%0,%1,%2,%3}, [%4];" \
        : "=r"((r)[0]), "=r"((r)[1]), "=r"((r)[2]), "=r"((r)[3]) : "r"(addr))

#define IMMA_16832(c, a, b0, b1) \
    asm volatile("mma.sync.aligned.m16n8k32.row.col.s32.s8.s8.s32 " \
        "{%0,%1,%2,%3}, {%4,%5,%6,%7}, {%8,%9}, {%0,%1,%2,%3};" \
        : "+r"((c)[0]), "+r"((c)[1]), "+r"((c)[2]), "+r"((c)[3]) \
        : "r"((a)[0]), "r"((a)[1]), "r"((a)[2]), "r"((a)[3]), "r"(b0), "r"(b1))

// ---------------------------------------------------------------------------
// prep: fused norms + scales + int8 quantization (one warp per row)
// ---------------------------------------------------------------------------
__global__ void __launch_bounds__(256) vq_prep(const float* __restrict__ x,
                                               const float* __restrict__ emb) {
    if (blockIdx.x == 0 && threadIdx.x == 0) g_losssum = 0.0;
    int warp = threadIdx.x >> 5;
    int lane = threadIdx.x & 31;
    int row = blockIdx.x * 8 + warp;
    const float* src;
    float *norm_dst, *scale_dst;
    uint2* q_dst;
    float sfac;
    if (row < NE) {
        src = emb + (size_t)row * DIM;
        norm_dst = g_enorm + row; scale_dst = g_escale + row;
        q_dst = g_eq + (size_t)row * 32;
        sfac = -2.0f / 127.0f;               // fold -2*se
    } else {
        int r = row - NE;
        if (r >= NROWS) return;
        src = x + (size_t)r * DIM;
        norm_dst = g_xnorm + r; scale_dst = g_xscale + r;
        q_dst = g_xq + (size_t)r * 32;
        sfac = 1.0f / 127.0f;
    }
    const float4* p = (const float4*)src;
    float4 v0 = p[lane * 2];
    float4 v1 = p[lane * 2 + 1];
    float s = v0.x*v0.x + v0.y*v0.y + v0.z*v0.z + v0.w*v0.w
            + v1.x*v1.x + v1.y*v1.y + v1.z*v1.z + v1.w*v1.w;
    #pragma unroll
    for (int o = 16; o > 0; o >>= 1)
        s += __shfl_down_sync(0xffffffffu, s, o);

    float f[8] = {v0.x, v0.y, v0.z, v0.w, v1.x, v1.y, v1.z, v1.w};
    float m = 0.0f;
    #pragma unroll
    for (int i = 0; i < 8; i++) m = fmaxf(m, fabsf(f[i]));
    #pragma unroll
    for (int o = 16; o > 0; o >>= 1)
        m = fmaxf(m, __shfl_xor_sync(0xffffffffu, m, o));

    float inv = 127.0f / m;
    int q[8];
    #pragma unroll
    for (int i = 0; i < 8; i++) {
        int v = __float2int_rn(f[i] * inv);
        q[i] = max(-127, min(127, v));
    }
    uint2 packed;
    packed.x = (q[0] & 0xff) | ((q[1] & 0xff) << 8) |
               ((q[2] & 0xff) << 16) | ((q[3] & 0xff) << 24);
    packed.y = (q[4] & 0xff) | ((q[5] & 0xff) << 8) |
               ((q[6] & 0xff) << 16) | ((q[7] & 0xff) << 24);
    q_dst[lane] = packed;
    if (lane == 0) {
        *norm_dst = s;
        *scale_dst = m * sfac;
    }
}

// ---------------------------------------------------------------------------
// Main IMMA kernel: int8 K=256, occupancy 2, lean epilogue.
// d = fmaf(S*es2, sx, xn+en); plain scattered streaming stores;
// top-3 via packed sortable u64 keys (d>0 always; low 13 bits = index,
// so min-u64 also gives lowest-index tie-break).
// ---------------------------------------------------------------------------
#define BM 128
#define BN 128
#define NCH 2
#define NT  (NE / BN)          // 64
#define NQ  (NT * NCH)         // 128
#define SM_A 0
#define SM_B 32768
#define SMEM_TOTAL 81920       // 32KB A + 3*16KB B (x2 CTAs = 160KB)

__global__ void __launch_bounds__(256, 2) vq_main_imma(float* __restrict__ out) {
    extern __shared__ char smem[];
    const uint32_t smem_u32 = smem_to_u32(smem);
    const uint32_t Ab = smem_u32 + SM_A;
    const int tid = threadIdx.x;
    const int lane = tid & 31;
    const int wid = tid >> 5;
    const int wm = wid & 3;
    const int wn = wid >> 2;
    const int g = lane >> 2;
    const int t = lane & 3;
    const int m0 = blockIdx.x * BM;

    const uint64_t xq_g = to_global(g_xq);
    const uint64_t eq_g = to_global(g_eq);

    // A load: 128 rows x 16 16B-chunks (32KB)
    #pragma unroll
    for (int i = 0; i < 8; i++) {
        int idx = tid + i * 256;
        int row = idx >> 4;
        int ch  = idx & 15;
        uint64_t src = xq_g + ((uint64_t)(m0 + row)) * 256 + ch * 16;
        uint32_t dst = Ab + row * 256 + ((ch ^ (row & 7)) << 4);
        CP_ASYNC_16(dst, src);
    }
    CP_COMMIT();

    // B prologue: chunks 0,1 into stages 0,1
    #pragma unroll
    for (int p = 0; p < 2; p++) {
        uint32_t dstb = smem_u32 + SM_B + p * 16384;
        #pragma unroll
        for (int i = 0; i < 4; i++) {
            int idx = tid + i * 256;
            int row = idx >> 3;
            int ch  = idx & 7;
            uint64_t src = eq_g + ((uint64_t)row) * 256 + p * 128 + ch * 16;
            uint32_t dst = dstb + row * 128 + ((ch ^ (row & 7)) << 4);
            CP_ASYNC_16(dst, src);
        }
        CP_COMMIT();
    }

    float xnv[4], sxv[4];
    #pragma unroll
    for (int ii = 0; ii < 4; ii++) {
        int grow = m0 + wm * 32 + (ii >> 1) * 16 + (ii & 1) * 8 + g;
        xnv[ii] = g_xnorm[grow];
        sxv[ii] = g_xscale[grow];
    }
    uint64_t k1[4], k2[4], k3[4];
    #pragma unroll
    for (int ii = 0; ii < 4; ii++) {
        k1[ii] = ~0ull; k2[ii] = ~0ull; k3[ii] = ~0ull;
    }

    int q = 0;
    int sfill = 2, suse = 0;
    for (int n = 0; n < NT; n++) {
        const int n0 = n * BN;
        int acc[2][8][4];
        #pragma unroll
        for (int i = 0; i < 2; i++)
            #pragma unroll
            for (int j = 0; j < 8; j++)
                #pragma unroll
                for (int r = 0; r < 4; r++) acc[i][j][r] = 0;

        #pragma unroll
        for (int c = 0; c < NCH; c++, q++) {
            CP_WAIT(1);
            __syncthreads();

            int qi = q + 2;
            if (qi < NQ) {
                int nn = qi >> 1, cc = qi & 1;
                uint32_t dstb = smem_u32 + SM_B + sfill * 16384;
                #pragma unroll
                for (int i = 0; i < 4; i++) {
                    int idx = tid + i * 256;
                    int row = idx >> 3;
                    int ch  = idx & 7;
                    uint64_t src = eq_g + ((uint64_t)(nn * BN + row)) * 256 + cc * 128 + ch * 16;
                    uint32_t dst = dstb + row * 128 + ((ch ^ (row & 7)) << 4);
                    CP_ASYNC_16(dst, src);
                }
            }
            CP_COMMIT();
            sfill++; if (sfill == 3) sfill = 0;

            const uint32_t Bb = smem_u32 + SM_B + suse * 16384;
            suse++; if (suse == 3) suse = 0;
            #pragma unroll
            for (int ks = 0; ks < 4; ks++) {
                uint32_t a[2][4];
                #pragma unroll
                for (int i = 0; i < 2; i++) {
                    int row = wm * 32 + i * 16 + (lane & 15);
                    int ch = c * 8 + ks * 2 + (lane >> 4);
                    LDMATRIX_X4(a[i], Ab + row * 256 + ((ch ^ (row & 7)) << 4));
                }
                #pragma unroll
                for (int jj = 0; jj < 4; jj++) {
                    uint32_t b[4];
                    int nloc = wn * 64 + jj * 16 + (lane & 7) + ((lane >> 4) << 3);
                    int ch = ks * 2 + ((lane >> 3) & 1);
                    LDMATRIX_X4(b, Bb + nloc * 128 + ((ch ^ (nloc & 7)) << 4));
                    #pragma unroll
                    for (int i = 0; i < 2; i++) {
                        IMMA_16832(acc[i][jj * 2],     a[i], b[0], b[1]);
                        IMMA_16832(acc[i][jj * 2 + 1], a[i], b[2], b[3]);
                    }
                }
            }
        }

        // ---- lean epilogue ----
        const float* enb = g_enorm + n0 + wn * 64 + 2 * t;
        const float* seb = g_escale + n0 + wn * 64 + 2 * t;
        #pragma unroll
        for (int i = 0; i < 2; i++) {
            #pragma unroll
            for (int p = 0; p < 2; p++) {
                const int ii = i * 2 + p;
                const int grow = m0 + wm * 32 + i * 16 + p * 8 + g;
                const float xnr = xnv[ii];
                const float sx = sxv[ii];
                float* dbase = out + D_OFF + (size_t)grow * NE + n0 + wn * 64 + 2 * t;
                #pragma unroll
                for (int j = 0; j < 8; j++) {
                    float2 e2 = *(const float2*)(enb + j * 8);
                    float2 s2 = *(const float2*)(seb + j * 8);
                    float S0 = (float)acc[i][j][p * 2];
                    float S1 = (float)acc[i][j][p * 2 + 1];
                    float d0 = fmaf(S0 * s2.x, sx, xnr + e2.x);
                    float d1 = fmaf(S1 * s2.y, sx, xnr + e2.y);
                    __stcs(dbase + j * 8, d0);
                    __stcs(dbase + j * 8 + 1, d1);
                    uint32_t cidx = (uint32_t)(n0 + wn * 64 + j * 8 + 2 * t);
                    uint64_t ka = (((uint64_t)__float_as_uint(d0)) << 13) | cidx;
                    uint64_t kb = (((uint64_t)__float_as_uint(d1)) << 13) | (cidx + 1);
                    if (ka < k3[ii]) {
                        if (ka < k2[ii]) {
                            k3[ii] = k2[ii];
                            if (ka < k1[ii]) { k2[ii] = k1[ii]; k1[ii] = ka; }
                            else k2[ii] = ka;
                        } else k3[ii] = ka;
                    }
                    if (kb < k3[ii]) {
                        if (kb < k2[ii]) {
                            k3[ii] = k2[ii];
                            if (kb < k1[ii]) { k2[ii] = k1[ii]; k1[ii] = kb; }
                            else k2[ii] = kb;
                        } else k3[ii] = kb;
                    }
                }
            }
        }
    }

    // dump per-lane top-3 candidates (8 lane-slots per row x 3 = 24 per row)
    #pragma unroll
    for (int ii = 0; ii < 4; ii++) {
        int grow = m0 + wm * 32 + (ii >> 1) * 16 + (ii & 1) * 8 + g;
        int base = grow * 24 + (wn * 4 + t) * 3;
        g_cand[base]     = (int)(k1[ii] & 0x1fff);
        g_cand[base + 1] = (int)(k2[ii] & 0x1fff);
        g_cand[base + 2] = (int)(k3[ii] & 0x1fff);
    }
}

// ---------------------------------------------------------------------------
// Refine + gather + loss (fused). One warp per row, 24 candidates,
// coalesced emb loads, exact fp32 arithmetic (validated).
// ---------------------------------------------------------------------------
__global__ void __launch_bounds__(256) vq_refine(const float* __restrict__ x,
                                                 const float* __restrict__ emb,
                                                 float* __restrict__ out) {
    __shared__ double sd[8];
    const int warp = threadIdx.x >> 5;
    const int lane = threadIdx.x & 31;
    const int row = blockIdx.x * 8 + warp;

    const float4* xp = (const float4*)(x + (size_t)row * DIM);
    const float4 xa = xp[lane];
    const float4 xb = xp[lane + 32];
    const float xn = g_xnorm[row];

    float bv = 3.4e38f;
    int bi = 0x7fffffff;
    #pragma unroll 4
    for (int c = 0; c < 24; c++) {
        const int idx = g_cand[row * 24 + c];
        const float4* ep = (const float4*)(emb + (size_t)idx * DIM);
        float4 ea = __ldg(ep + lane);
        float4 eb = __ldg(ep + lane + 32);
        float s = xa.x * ea.x;
        s = __fmaf_rn(xa.y, ea.y, s);
        s = __fmaf_rn(xa.z, ea.z, s);
        s = __fmaf_rn(xa.w, ea.w, s);
        s = __fmaf_rn(xb.x, eb.x, s);
        s = __fmaf_rn(xb.y, eb.y, s);
        s = __fmaf_rn(xb.z, eb.z, s);
        s = __fmaf_rn(xb.w, eb.w, s);
        #pragma unroll
        for (int o = 16; o > 0; o >>= 1)
            s += __shfl_xor_sync(0xffffffffu, s, o);
        float dv = __fmaf_rn(-2.0f, s, __fadd_rn(xn, g_enorm[idx]));
        if (dv < bv || (dv == bv && idx < bi)) { bv = dv; bi = idx; }
    }
    if (lane == 0) out[IDX_OFF + row] = (float)bi;

    const float4* ep = (const float4*)(emb + (size_t)bi * DIM);
    float4 ea = __ldg(ep + lane);
    float4 eb = __ldg(ep + lane + 32);
    float4 o1, o2;
    float dax = ea.x - xa.x, day = ea.y - xa.y, daz = ea.z - xa.z, daw = ea.w - xa.w;
    float dbx = eb.x - xb.x, dby = eb.y - xb.y, dbz = eb.z - xb.z, dbw = eb.w - xb.w;
    o1.x = xa.x + dax; o1.y = xa.y + day; o1.z = xa.z + daz; o1.w = xa.w + daw;
    o2.x = xb.x + dbx; o2.y = xb.y + dby; o2.z = xb.z + dbz; o2.w = xb.w + dbw;
    float4* oq = (float4*)(out + XQ_OFF + (size_t)row * DIM);
    oq[lane] = o1;
    oq[lane + 32] = o2;

    float s2 = dax*dax + day*day + daz*daz + daw*daw
             + dbx*dbx + dby*dby + dbz*dbz + dbw*dbw;
    #pragma unroll
    for (int o = 16; o > 0; o >>= 1)
        s2 += __shfl_down_sync(0xffffffffu, s2, o);
    if (lane == 0) sd[warp] = (double)s2;
    __syncthreads();
    if (threadIdx.x == 0) {
        double bs = 0.0;
        #pragma unroll
        for (int w = 0; w < 8; w++) bs += sd[w];
        atomicAdd(&g_losssum, bs);
    }
}

__global__ void vq_loss(float* __restrict__ out) {
    double mse = g_losssum / (double)(NROWS * DIM);
    out[LOSS_OFF] = (float)(1.25 * mse);
}

// ---------------------------------------------------------------------------
extern "C" void kernel_launch(void* const* d_in, const int* in_sizes, int n_in,
                              void* d_out, int out_size) {
    const float* x = (const float*)d_in[0];
    const float* emb = (const float*)d_in[1];
    float* out = (float*)d_out;
    (void)in_sizes; (void)n_in; (void)out_size;

    static bool attr_set = false;
    if (!attr_set) {
        cudaFuncSetAttribute(vq_main_imma, cudaFuncAttributeMaxDynamicSharedMemorySize,
                             SMEM_TOTAL);
        attr_set = true;
    }

    vq_prep<<<(NE + NROWS) / 8, 256>>>(x, emb);
    vq_main_imma<<<NROWS / BM, 256, SMEM_TOTAL>>>(out);
    vq_refine<<<NROWS / 8, 256>>>(x, emb, out);
    vq_loss<<<1, 1>>>(out);
}

// round 11
// speedup vs baseline: 1.7715x; 1.7715x over previous
#include <cuda_runtime.h>
#include <cuda_fp16.h>
#include <cstdint>

// Problem constants
#define NROWS 65536
#define DIM   256
#define NE    8192

// Output packing (float32, reference return order)
#define XQ_OFF   0ULL
#define LOSS_OFF 16777216ULL
#define IDX_OFF  16777217ULL
#define D_OFF    16842753ULL

// ---------------------------------------------------------------------------
// Device scratch
// ---------------------------------------------------------------------------
__device__ uint4 g_xh[NROWS * 32];   // fp16 x rows (32MB)
__device__ uint4 g_eh[NE * 32];      // fp16 emb rows, pre-scaled by 4096 (4MB)
__device__ __align__(16) float g_xnorm[NROWS];
__device__ __align__(16) float g_enorm[NE];
__device__ int    g_cand[NROWS * 16];   // 16 argmin candidates per row (4MB)
__device__ double g_losssum;

// ---------------------------------------------------------------------------
// helpers
// ---------------------------------------------------------------------------
__device__ __forceinline__ uint32_t smem_to_u32(const void* p) {
    uint32_t a;
    asm("{ .reg .u64 t; cvta.to.shared.u64 t, %1; cvt.u32.u64 %0, t; }"
        : "=r"(a) : "l"(p));
    return a;
}
__device__ __forceinline__ uint64_t to_global(const void* p) {
    uint64_t g;
    asm("cvta.to.global.u64 %0, %1;" : "=l"(g) : "l"(p));
    return g;
}
#define CP_ASYNC_16(dst, src) \
    asm volatile("cp.async.cg.shared.global [%0], [%1], 16;" :: "r"(dst), "l"(src))
#define CP_COMMIT() asm volatile("cp.async.commit_group;" ::: "memory")
#define CP_WAIT(n)  asm volatile("cp.async.wait_group %0;" :: "n"(n) : "memory")

#define LDMATRIX_X4(r, addr) \
    asm volatile("ldmatrix.sync.aligned.m8n8.x4.shared.b16 {%0,%1,%2,%3}, [%4];" \
        : "=r"((r)[0]), "=r"((r)[1]), "=r"((r)[2]), "=r"((r)[3]) : "r"(addr))

#define MMA_16816(c, a, b0, b1) \
    asm volatile("mma.sync.aligned.m16n8k16.row.col.f32.f16.f16.f32 " \
        "{%0,%1,%2,%3}, {%4,%5,%6,%7}, {%8,%9}, {%0,%1,%2,%3};" \
        : "+f"((c)[0]), "+f"((c)[1]), "+f"((c)[2]), "+f"((c)[3]) \
        : "r"((a)[0]), "r"((a)[1]), "r"((a)[2]), "r"((a)[3]), "r"(b0), "r"(b1))

__device__ __forceinline__ uint32_t pack_half2(__half lo, __half hi) {
    return (uint32_t)__half_as_ushort(lo) | ((uint32_t)__half_as_ushort(hi) << 16);
}

// ---------------------------------------------------------------------------
// prep: fp32 -> fp16 (emb scaled by 4096)
// ---------------------------------------------------------------------------
__global__ void __launch_bounds__(256) vq_prep(const float* __restrict__ x,
                                               const float* __restrict__ emb) {
    int gid = blockIdx.x * 256 + threadIdx.x;
    const float* src;
    uint4* dst;
    float sc;
    if (gid < NROWS * 32) {
        src = x + (size_t)gid * 8; dst = g_xh + gid; sc = 1.0f;
    } else {
        int g2 = gid - NROWS * 32;
        if (g2 >= NE * 32) return;
        src = emb + (size_t)g2 * 8; dst = g_eh + g2; sc = 4096.0f;
    }
    float4 v0 = ((const float4*)src)[0];
    float4 v1 = ((const float4*)src)[1];
    __half h[8];
    h[0] = __float2half_rn(v0.x * sc); h[1] = __float2half_rn(v0.y * sc);
    h[2] = __float2half_rn(v0.z * sc); h[3] = __float2half_rn(v0.w * sc);
    h[4] = __float2half_rn(v1.x * sc); h[5] = __float2half_rn(v1.y * sc);
    h[6] = __float2half_rn(v1.z * sc); h[7] = __float2half_rn(v1.w * sc);
    uint4 u;
    u.x = pack_half2(h[0], h[1]); u.y = pack_half2(h[2], h[3]);
    u.z = pack_half2(h[4], h[5]); u.w = pack_half2(h[6], h[7]);
    *dst = u;
}

// ---------------------------------------------------------------------------
// norms + loss reset
// ---------------------------------------------------------------------------
__global__ void __launch_bounds__(256) vq_norms(const float* __restrict__ x,
                                                const float* __restrict__ emb) {
    if (blockIdx.x == 0 && threadIdx.x == 0) g_losssum = 0.0;
    int warp = threadIdx.x >> 5;
    int lane = threadIdx.x & 31;
    int row = blockIdx.x * 8 + warp;
    const float* src; float* dst;
    if (row < NE) { src = emb + (size_t)row * DIM; dst = g_enorm + row; }
    else {
        int r = row - NE;
        if (r >= NROWS) return;
        src = x + (size_t)r * DIM; dst = g_xnorm + r;
    }
    const float4* p = (const float4*)src;
    float4 v0 = p[lane * 2];
    float4 v1 = p[lane * 2 + 1];
    float s = v0.x*v0.x + v0.y*v0.y + v0.z*v0.z + v0.w*v0.w
            + v1.x*v1.x + v1.y*v1.y + v1.z*v1.z + v1.w*v1.w;
    #pragma unroll
    for (int o = 16; o > 0; o >>= 1)
        s += __shfl_down_sync(0xffffffffu, s, o);
    if (lane == 0) *dst = s;
}

// ---------------------------------------------------------------------------
// Main HMMA kernel: K=256 fp16, occupancy 2, paired float2 streaming stores.
// ---------------------------------------------------------------------------
#define BM 128
#define BN 128
#define NCH 4
#define NT  (NE / BN)          // 64
#define NQ  (NT * NCH)         // 256
#define SM_A 0
#define SM_B 65536
#define SMEM_TOTAL 114688      // 64KB A + 3*16KB B (x2 CTAs = 224KB)

__global__ void __launch_bounds__(256, 2) vq_main_mma(float* __restrict__ out) {
    extern __shared__ char smem[];
    const uint32_t smem_u32 = smem_to_u32(smem);
    const uint32_t Ab = smem_u32 + SM_A;
    const int tid = threadIdx.x;
    const int lane = tid & 31;
    const int wid = tid >> 5;
    const int wm = wid & 3;
    const int wn = wid >> 2;
    const int g = lane >> 2;
    const int t = lane & 3;
    const int m0 = blockIdx.x * BM;

    const uint64_t xh_g = to_global(g_xh);
    const uint64_t eh_g = to_global(g_eh);

    // A load: 128 rows x 32 16B-chunks
    #pragma unroll
    for (int i = 0; i < 16; i++) {
        int idx = tid + i * 256;
        int row = idx >> 5;
        int ch  = idx & 31;
        uint64_t src = xh_g + (((uint64_t)(m0 + row)) * 32 + ch) * 16;
        uint32_t dst = Ab + row * 512 + ((ch ^ (row & 7)) << 4);
        CP_ASYNC_16(dst, src);
    }
    CP_COMMIT();

    // B prologue: chunks 0,1 into stages 0,1
    #pragma unroll
    for (int p = 0; p < 2; p++) {
        uint32_t dstb = smem_u32 + SM_B + p * 16384;
        #pragma unroll
        for (int i = 0; i < 4; i++) {
            int idx = tid + i * 256;
            int row = idx >> 3;
            int ch  = idx & 7;
            uint64_t src = eh_g + (((uint64_t)row) * 32 + p * 8 + ch) * 16;
            uint32_t dst = dstb + row * 128 + ((ch ^ (row & 7)) << 4);
            CP_ASYNC_16(dst, src);
        }
        CP_COMMIT();
    }

    float xnv[4];
    #pragma unroll
    for (int ii = 0; ii < 4; ii++)
        xnv[ii] = g_xnorm[m0 + wm * 32 + (ii >> 1) * 16 + (ii & 1) * 8 + g];
    float mv1[4] = {3.4e38f, 3.4e38f, 3.4e38f, 3.4e38f};
    float mv2[4] = {3.4e38f, 3.4e38f, 3.4e38f, 3.4e38f};
    int   mi1[4] = {0, 0, 0, 0};
    int   mi2[4] = {0, 0, 0, 0};

    int q = 0;
    int sfill = 2, suse = 0;
    for (int n = 0; n < NT; n++) {
        const int n0 = n * BN;
        float acc[2][8][4];
        #pragma unroll
        for (int i = 0; i < 2; i++)
            #pragma unroll
            for (int j = 0; j < 8; j++)
                #pragma unroll
                for (int r = 0; r < 4; r++) acc[i][j][r] = 0.0f;

        #pragma unroll
        for (int c = 0; c < NCH; c++, q++) {
            CP_WAIT(1);
            __syncthreads();

            int qi = q + 2;
            if (qi < NQ) {
                int nn = qi >> 2, cc = qi & 3;
                uint32_t dstb = smem_u32 + SM_B + sfill * 16384;
                #pragma unroll
                for (int i = 0; i < 4; i++) {
                    int idx = tid + i * 256;
                    int row = idx >> 3;
                    int ch  = idx & 7;
                    uint64_t src = eh_g + (((uint64_t)(nn * BN + row)) * 32 + cc * 8 + ch) * 16;
                    uint32_t dst = dstb + row * 128 + ((ch ^ (row & 7)) << 4);
                    CP_ASYNC_16(dst, src);
                }
            }
            CP_COMMIT();
            sfill++; if (sfill == 3) sfill = 0;

            const uint32_t Bb = smem_u32 + SM_B + suse * 16384;
            suse++; if (suse == 3) suse = 0;
            const int aK = c * 8;
            #pragma unroll
            for (int ks = 0; ks < 4; ks++) {
                uint32_t a[2][4];
                #pragma unroll
                for (int i = 0; i < 2; i++) {
                    int row = wm * 32 + i * 16 + (lane & 15);
                    int ch = aK + ks * 2 + (lane >> 4);
                    LDMATRIX_X4(a[i], Ab + row * 512 + ((ch ^ (row & 7)) << 4));
                }
                #pragma unroll
                for (int jj = 0; jj < 4; jj++) {
                    uint32_t b[4];
                    int nloc = wn * 64 + jj * 16 + (lane & 7) + ((lane >> 4) << 3);
                    int ch = ks * 2 + ((lane >> 3) & 1);
                    LDMATRIX_X4(b, Bb + nloc * 128 + ((ch ^ (nloc & 7)) << 4));
                    #pragma unroll
                    for (int i = 0; i < 2; i++) {
                        MMA_16816(acc[i][jj * 2],     a[i], b[0], b[1]);
                        MMA_16816(acc[i][jj * 2 + 1], a[i], b[2], b[3]);
                    }
                }
            }
        }

        // ---- epilogue: paired float2 streaming stores + top-2 tracking ----
        const float* enb = g_enorm + n0 + wn * 64 + 2 * t;
        #pragma unroll
        for (int i = 0; i < 2; i++) {
            #pragma unroll
            for (int p = 0; p < 2; p++) {
                const int ii = i * 2 + p;
                const int grow = m0 + wm * 32 + i * 16 + p * 8 + g;
                const float xnr = xnv[ii];
                float* drow = out + D_OFF + (size_t)grow * NE + n0 + wn * 64;
                float prev_d1 = 0.0f;
                #pragma unroll
                for (int j = 0; j < 8; j++) {
                    float2 e2 = *(const float2*)(enb + j * 8);
                    float S0 = acc[i][j][p * 2];
                    float S1 = acc[i][j][p * 2 + 1];
                    float d0 = fmaf(S0, -4.8828125e-4f, xnr + e2.x);
                    float d1 = fmaf(S1, -4.8828125e-4f, xnr + e2.y);
                    int cidx = n0 + wn * 64 + j * 8 + 2 * t;
                    if (d0 < mv2[ii]) {
                        if (d0 < mv1[ii]) { mv2[ii]=mv1[ii]; mi2[ii]=mi1[ii];
                                            mv1[ii]=d0; mi1[ii]=cidx; }
                        else { mv2[ii]=d0; mi2[ii]=cidx; }
                    }
                    if (d1 < mv2[ii]) {
                        if (d1 < mv1[ii]) { mv2[ii]=mv1[ii]; mi2[ii]=mi1[ii];
                                            mv1[ii]=d1; mi1[ii]=cidx+1; }
                        else { mv2[ii]=d1; mi2[ii]=cidx+1; }
                    }
                    // paired aligned stores: rot = d0 of group-lane (t+1)&3
                    float rot = __shfl_sync(0xffffffffu, d0, t + 1, 4);
                    if (t < 3) {
                        float2 v = make_float2(d1, rot);
                        __stcs((float2*)(drow + j * 8 + 2 * t + 1), v);
                    } else if (j > 0) {
                        float2 v = make_float2(prev_d1, rot);
                        __stcs((float2*)(drow + (j - 1) * 8 + 7), v);
                    }
                    if (t == 0 && j == 0) __stcs(drow, d0);
                    prev_d1 = d1;
                }
                if (t == 3) __stcs(drow + 63, prev_d1);
            }
        }
    }

    // dump per-lane top-2 candidates (8 lanes per row x 2 = 16 per row)
    #pragma unroll
    for (int ii = 0; ii < 4; ii++) {
        int grow = m0 + wm * 32 + (ii >> 1) * 16 + (ii & 1) * 8 + g;
        int base = grow * 16 + (wn * 4 + t) * 2;
        g_cand[base]     = mi1[ii];
        g_cand[base + 1] = mi2[ii];
    }
}

// ---------------------------------------------------------------------------
// Refine + gather + loss (fused). One warp per row; coalesced candidate loads.
// ---------------------------------------------------------------------------
__global__ void __launch_bounds__(256) vq_refine(const float* __restrict__ x,
                                                 const float* __restrict__ emb,
                                                 float* __restrict__ out) {
    __shared__ double sd[8];
    const int warp = threadIdx.x >> 5;
    const int lane = threadIdx.x & 31;
    const int row = blockIdx.x * 8 + warp;

    const float4* xp = (const float4*)(x + (size_t)row * DIM);
    const float4 xa = xp[lane];
    const float4 xb = xp[lane + 32];
    const float xn = g_xnorm[row];

    float bv = 3.4e38f;
    int bi = 0x7fffffff;
    #pragma unroll 4
    for (int c = 0; c < 16; c++) {
        const int idx = g_cand[row * 16 + c];
        const float4* ep = (const float4*)(emb + (size_t)idx * DIM);
        float4 ea = __ldg(ep + lane);
        float4 eb = __ldg(ep + lane + 32);
        float s = xa.x * ea.x;
        s = __fmaf_rn(xa.y, ea.y, s);
        s = __fmaf_rn(xa.z, ea.z, s);
        s = __fmaf_rn(xa.w, ea.w, s);
        s = __fmaf_rn(xb.x, eb.x, s);
        s = __fmaf_rn(xb.y, eb.y, s);
        s = __fmaf_rn(xb.z, eb.z, s);
        s = __fmaf_rn(xb.w, eb.w, s);
        #pragma unroll
        for (int o = 16; o > 0; o >>= 1)
            s += __shfl_xor_sync(0xffffffffu, s, o);
        float dv = __fmaf_rn(-2.0f, s, __fadd_rn(xn, g_enorm[idx]));
        if (dv < bv || (dv == bv && idx < bi)) { bv = dv; bi = idx; }
    }
    if (lane == 0) out[IDX_OFF + row] = (float)bi;

    const float4* ep = (const float4*)(emb + (size_t)bi * DIM);
    float4 ea = __ldg(ep + lane);
    float4 eb = __ldg(ep + lane + 32);
    float4 o1, o2;
    float dax = ea.x - xa.x, day = ea.y - xa.y, daz = ea.z - xa.z, daw = ea.w - xa.w;
    float dbx = eb.x - xb.x, dby = eb.y - xb.y, dbz = eb.z - xb.z, dbw = eb.w - xb.w;
    o1.x = xa.x + dax; o1.y = xa.y + day; o1.z = xa.z + daz; o1.w = xa.w + daw;
    o2.x = xb.x + dbx; o2.y = xb.y + dby; o2.z = xb.z + dbz; o2.w = xb.w + dbw;
    float4* oq = (float4*)(out + XQ_OFF + (size_t)row * DIM);
    oq[lane] = o1;
    oq[lane + 32] = o2;

    float s2 = dax*dax + day*day + daz*daz + daw*daw
             + dbx*dbx + dby*dby + dbz*dbz + dbw*dbw;
    #pragma unroll
    for (int o = 16; o > 0; o >>= 1)
        s2 += __shfl_down_sync(0xffffffffu, s2, o);
    if (lane == 0) sd[warp] = (double)s2;
    __syncthreads();
    if (threadIdx.x == 0) {
        double bs = 0.0;
        #pragma unroll
        for (int w = 0; w < 8; w++) bs += sd[w];
        atomicAdd(&g_losssum, bs);
    }
}

__global__ void vq_loss(float* __restrict__ out) {
    double mse = g_losssum / (double)(NROWS * DIM);
    out[LOSS_OFF] = (float)(1.25 * mse);
}

// ---------------------------------------------------------------------------
extern "C" void kernel_launch(void* const* d_in, const int* in_sizes, int n_in,
                              void* d_out, int out_size) {
    const float* x = (const float*)d_in[0];
    const float* emb = (const float*)d_in[1];
    float* out = (float*)d_out;
    (void)in_sizes; (void)n_in; (void)out_size;

    static bool attr_set = false;
    if (!attr_set) {
        cudaFuncSetAttribute(vq_main_mma, cudaFuncAttributeMaxDynamicSharedMemorySize,
                             SMEM_TOTAL);
        attr_set = true;
    }

    vq_prep<<<(NROWS + NE) * 32 / 256, 256>>>(x, emb);
    vq_norms<<<(NE + NROWS) / 8, 256>>>(x, emb);
    vq_main_mma<<<NROWS / BM, 256, SMEM_TOTAL>>>(out);
    vq_refine<<<NROWS / 8, 256>>>(x, emb, out);
    vq_loss<<<1, 1>>>(out);
}

// round 12
// speedup vs baseline: 1.8585x; 1.0491x over previous
#include <cuda_runtime.h>
#include <cuda_fp16.h>
#include <cstdint>

// Problem constants
#define NROWS 65536
#define DIM   256
#define NE    8192

// Output packing (float32, reference return order)
#define XQ_OFF   0ULL
#define LOSS_OFF 16777216ULL
#define IDX_OFF  16777217ULL
#define D_OFF    16842753ULL

// ---------------------------------------------------------------------------
// Device scratch
// ---------------------------------------------------------------------------
__device__ uint4 g_xh[NROWS * 32];   // fp16 x rows (32MB)
__device__ uint4 g_eh[NE * 32];      // fp16 emb rows, pre-scaled by 4096 (4MB)
__device__ __align__(16) float g_xnorm[NROWS];
__device__ __align__(16) float g_enorm[NE];
__device__ int    g_cand[NROWS * 24];   // 24 argmin candidates per row (6MB)
__device__ double g_losssum;

// ---------------------------------------------------------------------------
// helpers
// ---------------------------------------------------------------------------
__device__ __forceinline__ uint32_t smem_to_u32(const void* p) {
    uint32_t a;
    asm("{ .reg .u64 t; cvta.to.shared.u64 t, %1; cvt.u32.u64 %0, t; }"
        : "=r"(a) : "l"(p));
    return a;
}
__device__ __forceinline__ uint64_t to_global(const void* p) {
    uint64_t g;
    asm("cvta.to.global.u64 %0, %1;" : "=l"(g) : "l"(p));
    return g;
}
#define CP_ASYNC_16(dst, src) \
    asm volatile("cp.async.cg.shared.global [%0], [%1], 16;" :: "r"(dst), "l"(src))
#define CP_COMMIT() asm volatile("cp.async.commit_group;" ::: "memory")
#define CP_WAIT(n)  asm volatile("cp.async.wait_group %0;" :: "n"(n) : "memory")

#define LDMATRIX_X4(r, addr) \
    asm volatile("ldmatrix.sync.aligned.m8n8.x4.shared.b16 {%0,%1,%2,%3}, [%4];" \
        : "=r"((r)[0]), "=r"((r)[1]), "=r"((r)[2]), "=r"((r)[3]) : "r"(addr))

// fp16-accumulate HMMA: C fragment = 2 regs (half2 per 8-row block)
#define MMA_16816_H(c, a, b0, b1) \
    asm volatile("mma.sync.aligned.m16n8k16.row.col.f16.f16.f16.f16 " \
        "{%0,%1}, {%2,%3,%4,%5}, {%6,%7}, {%0,%1};" \
        : "+r"((c)[0]), "+r"((c)[1]) \
        : "r"((a)[0]), "r"((a)[1]), "r"((a)[2]), "r"((a)[3]), "r"(b0), "r"(b1))

__device__ __forceinline__ uint32_t pack_half2(__half lo, __half hi) {
    return (uint32_t)__half_as_ushort(lo) | ((uint32_t)__half_as_ushort(hi) << 16);
}

// ---------------------------------------------------------------------------
// prep: fp32 -> fp16 (emb scaled by 4096)
// ---------------------------------------------------------------------------
__global__ void __launch_bounds__(256) vq_prep(const float* __restrict__ x,
                                               const float* __restrict__ emb) {
    int gid = blockIdx.x * 256 + threadIdx.x;
    const float* src;
    uint4* dst;
    float sc;
    if (gid < NROWS * 32) {
        src = x + (size_t)gid * 8; dst = g_xh + gid; sc = 1.0f;
    } else {
        int g2 = gid - NROWS * 32;
        if (g2 >= NE * 32) return;
        src = emb + (size_t)g2 * 8; dst = g_eh + g2; sc = 4096.0f;
    }
    float4 v0 = ((const float4*)src)[0];
    float4 v1 = ((const float4*)src)[1];
    __half h[8];
    h[0] = __float2half_rn(v0.x * sc); h[1] = __float2half_rn(v0.y * sc);
    h[2] = __float2half_rn(v0.z * sc); h[3] = __float2half_rn(v0.w * sc);
    h[4] = __float2half_rn(v1.x * sc); h[5] = __float2half_rn(v1.y * sc);
    h[6] = __float2half_rn(v1.z * sc); h[7] = __float2half_rn(v1.w * sc);
    uint4 u;
    u.x = pack_half2(h[0], h[1]); u.y = pack_half2(h[2], h[3]);
    u.z = pack_half2(h[4], h[5]); u.w = pack_half2(h[6], h[7]);
    *dst = u;
}

// ---------------------------------------------------------------------------
// norms + loss reset
// ---------------------------------------------------------------------------
__global__ void __launch_bounds__(256) vq_norms(const float* __restrict__ x,
                                                const float* __restrict__ emb) {
    if (blockIdx.x == 0 && threadIdx.x == 0) g_losssum = 0.0;
    int warp = threadIdx.x >> 5;
    int lane = threadIdx.x & 31;
    int row = blockIdx.x * 8 + warp;
    const float* src; float* dst;
    if (row < NE) { src = emb + (size_t)row * DIM; dst = g_enorm + row; }
    else {
        int r = row - NE;
        if (r >= NROWS) return;
        src = x + (size_t)r * DIM; dst = g_xnorm + r;
    }
    const float4* p = (const float4*)src;
    float4 v0 = p[lane * 2];
    float4 v1 = p[lane * 2 + 1];
    float s = v0.x*v0.x + v0.y*v0.y + v0.z*v0.z + v0.w*v0.w
            + v1.x*v1.x + v1.y*v1.y + v1.z*v1.z + v1.w*v1.w;
    #pragma unroll
    for (int o = 16; o > 0; o >>= 1)
        s += __shfl_down_sync(0xffffffffu, s, o);
    if (lane == 0) *dst = s;
}

// ---------------------------------------------------------------------------
// Main HMMA kernel: K=256 fp16, fp16 ACCUMULATE, occupancy 2,
// paired float2 streaming stores, per-lane top-3 candidates.
// ---------------------------------------------------------------------------
#define BM 128
#define BN 128
#define NCH 4
#define NT  (NE / BN)          // 64
#define NQ  (NT * NCH)         // 256
#define SM_A 0
#define SM_B 65536
#define SMEM_TOTAL 114688      // 64KB A + 3*16KB B (x2 CTAs = 224KB)

__global__ void __launch_bounds__(256, 2) vq_main_mma(float* __restrict__ out) {
    extern __shared__ char smem[];
    const uint32_t smem_u32 = smem_to_u32(smem);
    const uint32_t Ab = smem_u32 + SM_A;
    const int tid = threadIdx.x;
    const int lane = tid & 31;
    const int wid = tid >> 5;
    const int wm = wid & 3;
    const int wn = wid >> 2;
    const int g = lane >> 2;
    const int t = lane & 3;
    const int m0 = blockIdx.x * BM;

    const uint64_t xh_g = to_global(g_xh);
    const uint64_t eh_g = to_global(g_eh);

    // A load: 128 rows x 32 16B-chunks
    #pragma unroll
    for (int i = 0; i < 16; i++) {
        int idx = tid + i * 256;
        int row = idx >> 5;
        int ch  = idx & 31;
        uint64_t src = xh_g + (((uint64_t)(m0 + row)) * 32 + ch) * 16;
        uint32_t dst = Ab + row * 512 + ((ch ^ (row & 7)) << 4);
        CP_ASYNC_16(dst, src);
    }
    CP_COMMIT();

    // B prologue: chunks 0,1 into stages 0,1
    #pragma unroll
    for (int p = 0; p < 2; p++) {
        uint32_t dstb = smem_u32 + SM_B + p * 16384;
        #pragma unroll
        for (int i = 0; i < 4; i++) {
            int idx = tid + i * 256;
            int row = idx >> 3;
            int ch  = idx & 7;
            uint64_t src = eh_g + (((uint64_t)row) * 32 + p * 8 + ch) * 16;
            uint32_t dst = dstb + row * 128 + ((ch ^ (row & 7)) << 4);
            CP_ASYNC_16(dst, src);
        }
        CP_COMMIT();
    }

    float xnv[4];
    #pragma unroll
    for (int ii = 0; ii < 4; ii++)
        xnv[ii] = g_xnorm[m0 + wm * 32 + (ii >> 1) * 16 + (ii & 1) * 8 + g];
    float mv1[4] = {3.4e38f, 3.4e38f, 3.4e38f, 3.4e38f};
    float mv2[4] = {3.4e38f, 3.4e38f, 3.4e38f, 3.4e38f};
    float mv3[4] = {3.4e38f, 3.4e38f, 3.4e38f, 3.4e38f};
    int   mi1[4] = {0,0,0,0}, mi2[4] = {0,0,0,0}, mi3[4] = {0,0,0,0};

    int q = 0;
    int sfill = 2, suse = 0;
    for (int n = 0; n < NT; n++) {
        const int n0 = n * BN;
        // fp16 accumulators: [i][j][p] = half2 (col 2t, 2t+1) of row-block p
        uint32_t acc[2][8][2];
        #pragma unroll
        for (int i = 0; i < 2; i++)
            #pragma unroll
            for (int j = 0; j < 8; j++) {
                acc[i][j][0] = 0u; acc[i][j][1] = 0u;
            }

        #pragma unroll
        for (int c = 0; c < NCH; c++, q++) {
            CP_WAIT(1);
            __syncthreads();

            int qi = q + 2;
            if (qi < NQ) {
                int nn = qi >> 2, cc = qi & 3;
                uint32_t dstb = smem_u32 + SM_B + sfill * 16384;
                #pragma unroll
                for (int i = 0; i < 4; i++) {
                    int idx = tid + i * 256;
                    int row = idx >> 3;
                    int ch  = idx & 7;
                    uint64_t src = eh_g + (((uint64_t)(nn * BN + row)) * 32 + cc * 8 + ch) * 16;
                    uint32_t dst = dstb + row * 128 + ((ch ^ (row & 7)) << 4);
                    CP_ASYNC_16(dst, src);
                }
            }
            CP_COMMIT();
            sfill++; if (sfill == 3) sfill = 0;

            const uint32_t Bb = smem_u32 + SM_B + suse * 16384;
            suse++; if (suse == 3) suse = 0;
            const int aK = c * 8;
            #pragma unroll
            for (int ks = 0; ks < 4; ks++) {
                uint32_t a[2][4];
                #pragma unroll
                for (int i = 0; i < 2; i++) {
                    int row = wm * 32 + i * 16 + (lane & 15);
                    int ch = aK + ks * 2 + (lane >> 4);
                    LDMATRIX_X4(a[i], Ab + row * 512 + ((ch ^ (row & 7)) << 4));
                }
                #pragma unroll
                for (int jj = 0; jj < 4; jj++) {
                    uint32_t b[4];
                    int nloc = wn * 64 + jj * 16 + (lane & 7) + ((lane >> 4) << 3);
                    int ch = ks * 2 + ((lane >> 3) & 1);
                    LDMATRIX_X4(b, Bb + nloc * 128 + ((ch ^ (nloc & 7)) << 4));
                    #pragma unroll
                    for (int i = 0; i < 2; i++) {
                        MMA_16816_H(acc[i][jj * 2],     a[i], b[0], b[1]);
                        MMA_16816_H(acc[i][jj * 2 + 1], a[i], b[2], b[3]);
                    }
                }
            }
        }

        // ---- epilogue: unpack fp16 acc, paired stores, top-3 tracking ----
        const float* enb = g_enorm + n0 + wn * 64 + 2 * t;
        #pragma unroll
        for (int i = 0; i < 2; i++) {
            #pragma unroll
            for (int p = 0; p < 2; p++) {
                const int ii = i * 2 + p;
                const int grow = m0 + wm * 32 + i * 16 + p * 8 + g;
                const float xnr = xnv[ii];
                float* drow = out + D_OFF + (size_t)grow * NE + n0 + wn * 64;
                float prev_d1 = 0.0f;
                #pragma unroll
                for (int j = 0; j < 8; j++) {
                    float2 e2 = *(const float2*)(enb + j * 8);
                    float2 Sv = __half22float2(*(const __half2*)&acc[i][j][p]);
                    float d0 = fmaf(Sv.x, -4.8828125e-4f, xnr + e2.x);
                    float d1 = fmaf(Sv.y, -4.8828125e-4f, xnr + e2.y);
                    int cidx = n0 + wn * 64 + j * 8 + 2 * t;
                    if (d0 < mv3[ii]) {
                        if (d0 < mv2[ii]) {
                            mv3[ii]=mv2[ii]; mi3[ii]=mi2[ii];
                            if (d0 < mv1[ii]) { mv2[ii]=mv1[ii]; mi2[ii]=mi1[ii];
                                                mv1[ii]=d0; mi1[ii]=cidx; }
                            else { mv2[ii]=d0; mi2[ii]=cidx; }
                        } else { mv3[ii]=d0; mi3[ii]=cidx; }
                    }
                    if (d1 < mv3[ii]) {
                        if (d1 < mv2[ii]) {
                            mv3[ii]=mv2[ii]; mi3[ii]=mi2[ii];
                            if (d1 < mv1[ii]) { mv2[ii]=mv1[ii]; mi2[ii]=mi1[ii];
                                                mv1[ii]=d1; mi1[ii]=cidx+1; }
                            else { mv2[ii]=d1; mi2[ii]=cidx+1; }
                        } else { mv3[ii]=d1; mi3[ii]=cidx+1; }
                    }
                    // paired aligned stores
                    float rot = __shfl_sync(0xffffffffu, d0, t + 1, 4);
                    if (t < 3) {
                        float2 v = make_float2(d1, rot);
                        __stcs((float2*)(drow + j * 8 + 2 * t + 1), v);
                    } else if (j > 0) {
                        float2 v = make_float2(prev_d1, rot);
                        __stcs((float2*)(drow + (j - 1) * 8 + 7), v);
                    }
                    if (t == 0 && j == 0) __stcs(drow, d0);
                    prev_d1 = d1;
                }
                if (t == 3) __stcs(drow + 63, prev_d1);
            }
        }
    }

    // dump per-lane top-3 candidates (8 lane-slots per row x 3 = 24 per row)
    #pragma unroll
    for (int ii = 0; ii < 4; ii++) {
        int grow = m0 + wm * 32 + (ii >> 1) * 16 + (ii & 1) * 8 + g;
        int base = grow * 24 + (wn * 4 + t) * 3;
        g_cand[base]     = mi1[ii];
        g_cand[base + 1] = mi2[ii];
        g_cand[base + 2] = mi3[ii];
    }
}

// ---------------------------------------------------------------------------
// Refine + gather + loss (fused). One warp per row, 24 candidates,
// coalesced emb loads, exact fp32 arithmetic (validated).
// ---------------------------------------------------------------------------
__global__ void __launch_bounds__(256) vq_refine(const float* __restrict__ x,
                                                 const float* __restrict__ emb,
                                                 float* __restrict__ out) {
    __shared__ double sd[8];
    const int warp = threadIdx.x >> 5;
    const int lane = threadIdx.x & 31;
    const int row = blockIdx.x * 8 + warp;

    const float4* xp = (const float4*)(x + (size_t)row * DIM);
    const float4 xa = xp[lane];
    const float4 xb = xp[lane + 32];
    const float xn = g_xnorm[row];

    float bv = 3.4e38f;
    int bi = 0x7fffffff;
    #pragma unroll 4
    for (int c = 0; c < 24; c++) {
        const int idx = g_cand[row * 24 + c];
        const float4* ep = (const float4*)(emb + (size_t)idx * DIM);
        float4 ea = __ldg(ep + lane);
        float4 eb = __ldg(ep + lane + 32);
        float s = xa.x * ea.x;
        s = __fmaf_rn(xa.y, ea.y, s);
        s = __fmaf_rn(xa.z, ea.z, s);
        s = __fmaf_rn(xa.w, ea.w, s);
        s = __fmaf_rn(xb.x, eb.x, s);
        s = __fmaf_rn(xb.y, eb.y, s);
        s = __fmaf_rn(xb.z, eb.z, s);
        s = __fmaf_rn(xb.w, eb.w, s);
        #pragma unroll
        for (int o = 16; o > 0; o >>= 1)
            s += __shfl_xor_sync(0xffffffffu, s, o);
        float dv = __fmaf_rn(-2.0f, s, __fadd_rn(xn, g_enorm[idx]));
        if (dv < bv || (dv == bv && idx < bi)) { bv = dv; bi = idx; }
    }
    if (lane == 0) out[IDX_OFF + row] = (float)bi;

    const float4* ep = (const float4*)(emb + (size_t)bi * DIM);
    float4 ea = __ldg(ep + lane);
    float4 eb = __ldg(ep + lane + 32);
    float4 o1, o2;
    float dax = ea.x - xa.x, day = ea.y - xa.y, daz = ea.z - xa.z, daw = ea.w - xa.w;
    float dbx = eb.x - xb.x, dby = eb.y - xb.y, dbz = eb.z - xb.z, dbw = eb.w - xb.w;
    o1.x = xa.x + dax; o1.y = xa.y + day; o1.z = xa.z + daz; o1.w = xa.w + daw;
    o2.x = xb.x + dbx; o2.y = xb.y + dby; o2.z = xb.z + dbz; o2.w = xb.w + dbw;
    float4* oq = (float4*)(out + XQ_OFF + (size_t)row * DIM);
    oq[lane] = o1;
    oq[lane + 32] = o2;

    float s2 = dax*dax + day*day + daz*daz + daw*daw
             + dbx*dbx + dby*dby + dbz*dbz + dbw*dbw;
    #pragma unroll
    for (int o = 16; o > 0; o >>= 1)
        s2 += __shfl_down_sync(0xffffffffu, s2, o);
    if (lane == 0) sd[warp] = (double)s2;
    __syncthreads();
    if (threadIdx.x == 0) {
        double bs = 0.0;
        #pragma unroll
        for (int w = 0; w < 8; w++) bs += sd[w];
        atomicAdd(&g_losssum, bs);
    }
}

__global__ void vq_loss(float* __restrict__ out) {
    double mse = g_losssum / (double)(NROWS * DIM);
    out[LOSS_OFF] = (float)(1.25 * mse);
}

// ---------------------------------------------------------------------------
extern "C" void kernel_launch(void* const* d_in, const int* in_sizes, int n_in,
                              void* d_out, int out_size) {
    const float* x = (const float*)d_in[0];
    const float* emb = (const float*)d_in[1];
    float* out = (float*)d_out;
    (void)in_sizes; (void)n_in; (void)out_size;

    static bool attr_set = false;
    if (!attr_set) {
        cudaFuncSetAttribute(vq_main_mma, cudaFuncAttributeMaxDynamicSharedMemorySize,
                             SMEM_TOTAL);
        attr_set = true;
    }

    vq_prep<<<(NROWS + NE) * 32 / 256, 256>>>(x, emb);
    vq_norms<<<(NE + NROWS) / 8, 256>>>(x, emb);
    vq_main_mma<<<NROWS / BM, 256, SMEM_TOTAL>>>(out);
    vq_refine<<<NROWS / 8, 256>>>(x, emb, out);
    vq_loss<<<1, 1>>>(out);
}